// round 5
// baseline (speedup 1.0000x reference)
#include <cuda_runtime.h>
#include <stdint.h>

// ---------------- problem constants ----------------
#define A_TOTAL   159882
#define BS        2
#define NLEV      5
#define NTASK     (BS*NLEV)
#define NPAD      1024
#define NW        32
#define NB        8192         // histogram bins (top 13 bits of monotone key)
#define KSHIFT    19
#define TIECAP    2048
#define PRE_TOPN  1000
#define POST_TOPN 1000

__constant__ int c_offL[5] = {0,120000,150000,157500,159375};
__constant__ int c_nL[5]   = {120000,30000,7500,1875,507};
// blocks per task: A uses 256-thr blocks, B uses 1024-thr blocks
__constant__ int c_cbA[11] = {0,469,587,617,625,627,1096,1214,1244,1252,1254};
__constant__ int c_cbB[11] = {0,118,148,156,158,159,277,307,315,317,318};

// monotone key: larger float -> larger unsigned
__device__ __forceinline__ unsigned fkey(float f){
    unsigned u = __float_as_uint(f);
    return (u & 0x80000000u) ? ~u : (u | 0x80000000u);
}

// ---------------- scratch (device globals; zero-initialized at load) ----------------
__device__ __align__(16) unsigned            g_hist[NTASK*NB];      // 320 KB
__device__ int                               g_tieCnt[NTASK];
__device__ int                               g_selCnt[NTASK];
__device__ int                               g_thrBin[NTASK];
__device__ int                               g_doneA[NTASK];
__device__ int                               g_doneB[NTASK];
__device__ int                               g_doneD[BS];
__device__ __align__(16) unsigned long long  g_tie[NTASK*TIECAP];
__device__ __align__(16) unsigned long long  g_sel[NTASK*NPAD];
__device__ __align__(16) float4              g_boxes[NTASK*NPAD];
__device__ float                             g_scores[NTASK*NPAD];
__device__ unsigned                          g_keys[NTASK*NPAD];
__device__ unsigned                          g_validMask[NTASK*NW];
__device__ int                               g_kcnt[NTASK];
__device__ unsigned                          g_kkey[NTASK*NPAD];
__device__ int                               g_kref[NTASK*NPAD];

// =================== A: histogram + (last block) threshold scan ===================
__global__ void __launch_bounds__(256) kA(const float* __restrict__ obj){
    int b = blockIdx.x, tid = threadIdx.x;
    int t = 0;
    #pragma unroll
    for (int i=1;i<11;i++) if (b >= c_cbA[i]) t = i;
    int img = t/NLEV, lev = t - img*NLEV;
    int n = c_nL[lev];
    int local = (b - c_cbA[t])*256 + tid;
    if (local < n){
        unsigned key = fkey(obj[(size_t)img*A_TOTAL + c_offL[lev] + local]);
        atomicAdd(&g_hist[t*NB + (key >> KSHIFT)], 1u);
    }
    __threadfence();
    __syncthreads();
    __shared__ int slast;
    if (tid == 0){
        int tot = c_cbA[t+1] - c_cbA[t];
        slast = (atomicAdd(&g_doneA[t], 1) == tot-1) ? 1 : 0;
    }
    __syncthreads();
    if (!slast) return;

    // ---- scan phase (256 threads, 32 bins each) ----
    int k = n < PRE_TOPN ? n : PRE_TOPN;
    __shared__ unsigned ssum[256];
    const uint4* hb = (const uint4*)(g_hist + (size_t)t*NB + tid*32);
    uint4 h0=hb[0],h1=hb[1],h2=hb[2],h3=hb[3],h4=hb[4],h5=hb[5],h6=hb[6],h7=hb[7];
    unsigned own = h0.x+h0.y+h0.z+h0.w + h1.x+h1.y+h1.z+h1.w
                 + h2.x+h2.y+h2.z+h2.w + h3.x+h3.y+h3.z+h3.w
                 + h4.x+h4.y+h4.z+h4.w + h5.x+h5.y+h5.z+h5.w
                 + h6.x+h6.y+h6.z+h6.w + h7.x+h7.y+h7.z+h7.w;
    ssum[tid] = own;
    __syncthreads();
    for (int off=1; off<256; off<<=1){
        unsigned v = (tid+off<256) ? ssum[tid+off] : 0u;
        __syncthreads();
        ssum[tid] += v;
        __syncthreads();
    }
    unsigned above = (tid<255) ? ssum[tid+1] : 0u;
    if (k >= n){
        if (tid==0) g_thrBin[t] = -1;    // select all
    } else if (above < (unsigned)k && above + own >= (unsigned)k){
        unsigned c32[32] = {h0.x,h0.y,h0.z,h0.w, h1.x,h1.y,h1.z,h1.w,
                            h2.x,h2.y,h2.z,h2.w, h3.x,h3.y,h3.z,h3.w,
                            h4.x,h4.y,h4.z,h4.w, h5.x,h5.y,h5.z,h5.w,
                            h6.x,h6.y,h6.z,h6.w, h7.x,h7.y,h7.z,h7.w};
        unsigned cum = above; int res = -2;
        #pragma unroll
        for (int j=31;j>=0;j--){
            cum += c32[j];
            if (res == -2 && cum >= (unsigned)k) res = tid*32 + j;
        }
        g_thrBin[t] = res;
    }
    // zero my 32 bins (each thread read only its own), reset counter
    uint4 z = make_uint4(0,0,0,0);
    uint4* hw = (uint4*)(g_hist + (size_t)t*NB + tid*32);
    #pragma unroll
    for (int q=0;q<8;q++) hw[q] = z;
    if (tid == 0) g_doneA[t] = 0;
}

// =================== B: compaction + (last block) ties+sort+decode ===================
__global__ void __launch_bounds__(1024) kB(const float* __restrict__ pred,
                                           const float* __restrict__ obj,
                                           const float* __restrict__ anch,
                                           const float* __restrict__ vsz){
    int b = blockIdx.x, tid = threadIdx.x;
    int t = 0;
    #pragma unroll
    for (int i=1;i<11;i++) if (b >= c_cbB[i]) t = i;
    int img = t/NLEV, lev = t - img*NLEV;
    int n = c_nL[lev];
    int local = (b - c_cbB[t])*1024 + tid;
    int thr = g_thrBin[t];
    if (local < n){
        int a = c_offL[lev] + local;
        unsigned key = fkey(obj[(size_t)img*A_TOTAL + a]);
        int bin = (int)(key >> KSHIFT);
        if (bin >= thr){
            unsigned long long packed =
                ((unsigned long long)key << 32) | (unsigned long long)(0xFFFFFFFFu - (unsigned)a);
            if (bin > thr){
                int p = atomicAdd(&g_selCnt[t], 1);
                g_sel[t*NPAD + p] = packed;
            } else {
                int p = atomicAdd(&g_tieCnt[t], 1);
                if (p < TIECAP) g_tie[t*TIECAP + p] = packed;
            }
        }
    }
    __threadfence();
    __syncthreads();
    __shared__ int slast;
    if (tid == 0){
        int tot = c_cbB[t+1] - c_cbB[t];
        slast = (atomicAdd(&g_doneB[t], 1) == tot-1) ? 1 : 0;
    }
    __syncthreads();
    if (!slast) return;

    // ---- gather phase ----
    __shared__ unsigned long long ss[NPAD];       // 8 KB
    __shared__ unsigned long long sties[TIECAP];  // 16 KB
    int k = n < PRE_TOPN ? n : PRE_TOPN;
    int selCnt = g_selCnt[t];
    int tc = g_tieCnt[t]; if (tc > TIECAP) tc = TIECAP;
    int need = k - selCnt;
    ss[tid] = (tid < selCnt) ? g_sel[t*NPAD + tid] : 0ull;
    if (tid < tc) sties[tid] = g_tie[t*TIECAP + tid];
    if (tid + 1024 < tc) sties[tid+1024] = g_tie[t*TIECAP + tid + 1024];
    __syncthreads();
    if (need > 0){
        for (int i = tid; i < tc; i += 1024){
            unsigned long long mine = sties[i];
            int rank = 0;
            for (int j=0;j<tc;j++) rank += (sties[j] > mine);
            if (rank < need) ss[selCnt + rank] = mine;
        }
        __syncthreads();
    }
    // hybrid bitonic (descending): smem for stride>=32, shfl below
    unsigned long long v = ss[tid];
    for (int size=2; size<=NPAD; size<<=1){
        bool dirDesc = (tid & size) == 0;
        for (int stride=size>>1; stride>=32; stride>>=1){
            __syncthreads();
            ss[tid] = v;
            __syncthreads();
            unsigned long long o = ss[tid ^ stride];
            bool takeMax = (dirDesc == ((tid & stride) == 0));
            v = takeMax ? (v > o ? v : o) : (v < o ? v : o);
        }
        int s0 = (size>>1) < 16 ? (size>>1) : 16;
        for (int stride=s0; stride>=1; stride>>=1){
            unsigned long long o = __shfl_xor_sync(0xffffffffu, v, stride);
            bool takeMax = (dirDesc == ((tid & stride) == 0));
            v = takeMax ? (v > o ? v : o) : (v < o ? v : o);
        }
    }
    int r = tid;
    float4 box = make_float4(0.f,0.f,0.f,0.f);
    float score = 0.f; unsigned key = 0u; bool valid = false;
    if (r < k){
        key = (unsigned)(v >> 32);
        unsigned a = 0xFFFFFFFFu - (unsigned)(v & 0xFFFFFFFFull);
        float4 p  = __ldg(((const float4*)pred) + ((size_t)img*A_TOTAL + a));
        float4 an = __ldg(((const float4*)anch) + a);
        float awx = an.z - an.x, awy = an.w - an.y;
        float cx = an.x + 0.5f*awx + p.x*awx;
        float cy = an.y + 0.5f*awy + p.y*awy;
        float wx = expf(p.z)*awx;
        float wy = expf(p.w)*awy;
        float x1 = cx - 0.5f*wx, y1 = cy - 0.5f*wy;
        float x2 = x1 + wx,      y2 = y1 + wy;
        float W = vsz[img*2+0], H = vsz[img*2+1];
        x1 = fminf(fmaxf(x1,0.f),W); x2 = fminf(fmaxf(x2,0.f),W);
        y1 = fminf(fmaxf(y1,0.f),H); y2 = fminf(fmaxf(y2,0.f),H);
        box = make_float4(x1,y1,x2,y2);
        valid = (x2 - x1 > 0.001f) && (y2 - y1 > 0.001f);
        score = obj[(size_t)img*A_TOTAL + a];
    }
    g_boxes [t*NPAD + r] = box;
    g_scores[t*NPAD + r] = score;
    g_keys  [t*NPAD + r] = key;
    unsigned vm = __ballot_sync(0xffffffffu, valid);
    if ((tid & 31) == 0) g_validMask[t*NW + (tid>>5)] = vm;
    if (tid == 0){ g_selCnt[t] = 0; g_tieCnt[t] = 0; g_doneB[t] = 0; }
}

// =================== D: exact chunked greedy NMS (on-the-fly IoU) + merge ===================
__device__ __forceinline__ bool iou_gt(float4 a, float aa, float4 b, float ab){
    float xx1 = fmaxf(a.x, b.x);
    float yy1 = fmaxf(a.y, b.y);
    float xx2 = fminf(a.z, b.z);
    float yy2 = fminf(a.w, b.w);
    float iw = fmaxf(xx2-xx1, 0.f);
    float ih = fmaxf(yy2-yy1, 0.f);
    float inter = iw*ih;
    float den = aa + 1e-9f + ab - inter;
    return inter > 0.7f*den;            // == (iou > 0.7), den > 0
}

__global__ void __launch_bounds__(1024) kD(float* __restrict__ out){
    int task = blockIdx.x;
    int img = task / NLEV;
    int tid = threadIdx.x;
    int myw = tid >> 5, lane = tid & 31;

    __shared__ float4 sbox[NPAD];   // 16 KB
    __shared__ float  sar [NPAD];   //  4 KB
    __shared__ unsigned skeep[NW];
    float4 bi;
    {
        bi = g_boxes[task*NPAD + tid];
        sbox[tid] = bi;
        sar[tid]  = (bi.z - bi.x) * (bi.w - bi.y);
    }
    bool alive = (g_validMask[task*NW + myw] >> lane) & 1u;
    __syncthreads();
    float ai = sar[tid];

    // precompute intra-chunk suppression mask (box-data only, fully parallel):
    // diag bit j set => candidate (myw*32+j), j<lane, suppresses me if kept
    unsigned diag = 0u;
    int cb = myw*32;
    #pragma unroll 8
    for (int j=0; j<32; j++){
        bool o = (j < lane) && iou_gt(bi, ai, sbox[cb + j], sar[cb + j]);
        diag |= (o ? 1u : 0u) << j;
    }

    // sequential over 32 chunks; 1 barrier per chunk
    for (int c=0; c<NW; ++c){
        if (myw >= c){
            if (c > 0){
                unsigned m = skeep[c-1];           // kept set of previous chunk
                int pb = (c-1)*32;
                while (m){
                    int f = __ffs((int)m) - 1; m &= m - 1;
                    if (alive && iou_gt(bi, ai, sbox[pb + f], sar[pb + f])) alive = false;
                }
            }
            if (myw == c){
                // intra-chunk greedy resolution (warp c only)
                unsigned cand = __ballot_sync(0xffffffffu, alive);
                unsigned keptc = 0u;
                while (cand){
                    int f = __ffs((int)cand) - 1;
                    keptc |= (1u << f);
                    unsigned supf = __ballot_sync(0xffffffffu, (diag >> f) & 1u);
                    cand &= ~(supf | (1u << f));
                }
                alive = (keptc >> lane) & 1u;
                if (lane == 0) skeep[c] = keptc;
            }
        }
        __syncthreads();
    }

    // compaction (warp 0): kept list in score-descending order
    if (tid < 32){
        unsigned keepw = skeep[lane];
        unsigned cnt = __popc(keepw);
        unsigned incl = cnt;
        #pragma unroll
        for (int d=1; d<32; d<<=1){
            unsigned v2 = __shfl_up_sync(0xffffffffu, incl, d);
            if (lane >= d) incl += v2;
        }
        unsigned excl = incl - cnt;
        unsigned total = __shfl_sync(0xffffffffu, incl, 31);
        if (lane == 0) g_kcnt[task] = (int)total;
        unsigned m = keepw; int p = (int)excl;
        while (m){
            int bb = __ffs((int)m) - 1; m &= m - 1;
            int r = lane*32 + bb;
            g_kkey[task*NPAD + p] = g_keys[task*NPAD + r];
            g_kref[task*NPAD + p] = r;
            p++;
        }
    }
    __threadfence();
    __syncthreads();
    __shared__ int slastD;
    if (tid == 0) slastD = (atomicAdd(&g_doneD[img], 1) == NLEV-1) ? 1 : 0;
    __syncthreads();
    if (!slastD) return;
    if (tid == 0) g_doneD[img] = 0;

    // ---- merge phase: 5-way co-ranking merge for this image ----
    __shared__ unsigned skey[NLEV*NPAD];  // 20 KB
    __shared__ int scnt[NLEV];
    if (tid < NLEV) scnt[tid] = g_kcnt[img*NLEV + tid];
    for (int lt=0; lt<NLEV; lt++)
        skey[lt*NPAD + tid] = g_kkey[(img*NLEV + lt)*NPAD + tid];
    for (int i=tid; i<POST_TOPN*4; i+=1024) out[img*POST_TOPN*4 + i] = 0.f;
    for (int i=tid; i<POST_TOPN;   i+=1024) out[BS*POST_TOPN*4 + img*POST_TOPN + i] = 0.f;
    __syncthreads();
    for (int e=tid; e<NLEV*NPAD; e+=1024){
        int lt = e >> 10, p = e & (NPAD-1);
        if (p < scnt[lt]){
            unsigned key = skey[lt*NPAD + p];
            int rank = p;
            #pragma unroll
            for (int o=0; o<NLEV; o++){
                if (o == lt) continue;
                int cN = scnt[o];
                const unsigned* arr = skey + o*NPAD;
                int lo=0, hi=cN;
                while (lo < hi){
                    int mid = (lo+hi) >> 1;
                    bool before = (o < lt) ? (arr[mid] >= key) : (arr[mid] > key);
                    if (before) lo = mid+1; else hi = mid;
                }
                rank += lo;
            }
            if (rank < POST_TOPN){
                int t2 = img*NLEV + lt;
                int r = g_kref[t2*NPAD + p];
                float4 bb = g_boxes[t2*NPAD + r];
                float sc  = g_scores[t2*NPAD + r];
                float* ob = out + (img*POST_TOPN + rank)*4;
                ob[0]=bb.x; ob[1]=bb.y; ob[2]=bb.z; ob[3]=bb.w;
                out[BS*POST_TOPN*4 + img*POST_TOPN + rank] = sc;
            }
        }
    }
}

// ---------------- launch ----------------
extern "C" void kernel_launch(void* const* d_in, const int* in_sizes, int n_in,
                              void* d_out, int out_size){
    const float* pred = (const float*)d_in[0];   // (2, A, 4)
    const float* obj  = (const float*)d_in[1];   // (2, A, 1)
    const float* anch = (const float*)d_in[2];   // (A, 4)
    const float* vsz  = (const float*)d_in[3];   // (2, 2)
    float* out = (float*)d_out;                  // [boxes(2,1000,4) | scores(2,1000)]

    kA<<<1254, 256>>>(obj);
    kB<<<318, 1024>>>(pred, obj, anch, vsz);
    kD<<<NTASK, 1024>>>(out);
}

// round 6
// speedup vs baseline: 1.1178x; 1.1178x over previous
#include <cuda_runtime.h>
#include <stdint.h>

// ---------------- problem constants ----------------
#define A_TOTAL   159882
#define BS        2
#define NLEV      5
#define NTASK     (BS*NLEV)
#define NPAD      1024
#define NW        32
#define NB        8192         // histogram bins (top 13 bits of monotone key)
#define KSHIFT    19
#define TIECAP    2048
#define PRE_TOPN  1000
#define POST_TOPN 1000

// level boundaries: 120000,30000,7500,1875,507
__device__ __forceinline__ int levelOf(int a){
    if (a < 120000) return 0;
    if (a < 150000) return 1;
    if (a < 157500) return 2;
    if (a < 159375) return 3;
    return 4;
}
__device__ __forceinline__ int levN(int l){
    const int n0 = 120000, n1 = 30000, n2 = 7500, n3 = 1875, n4 = 507;
    return l==0?n0 : l==1?n1 : l==2?n2 : l==3?n3 : n4;
}

// monotone key: larger float -> larger unsigned
__device__ __forceinline__ unsigned fkey(float f){
    unsigned u = __float_as_uint(f);
    return (u & 0x80000000u) ? ~u : (u | 0x80000000u);
}

// ---------------- scratch (device globals; no allocation) ----------------
__device__ __align__(16) unsigned            g_hist[NTASK*NB];      // 320 KB
__device__ int                               g_tieCnt[NTASK];
__device__ int                               g_selCnt[NTASK];
__device__ int                               g_thrBin[NTASK];
__device__ __align__(16) unsigned long long  g_tie[NTASK*TIECAP];
__device__ __align__(16) unsigned long long  g_sel[NTASK*NPAD];
__device__ __align__(16) float4              g_boxes[NTASK*NPAD];
__device__ float                             g_scores[NTASK*NPAD];
__device__ unsigned                          g_keys[NTASK*NPAD];
__device__ unsigned                          g_validMask[NTASK*NW];
__device__ int                               g_kcnt[NTASK];
__device__ unsigned                          g_kkey[NTASK*NPAD];
__device__ int                               g_kref[NTASK*NPAD];

// ---------------- K0: zero histogram + counters ----------------
__global__ void k_zero(){
    int i = blockIdx.x*blockDim.x + threadIdx.x;
    if (i < NTASK*NB/4) ((uint4*)g_hist)[i] = make_uint4(0,0,0,0);
    if (i < NTASK){ g_tieCnt[i] = 0; g_selCnt[i] = 0; }
}

// ---------------- K1: per-task histogram (float4) ----------------
__global__ void k_hist(const float* __restrict__ obj){
    int q = blockIdx.x*blockDim.x + threadIdx.x;       // float4 index
    const int NQ = (BS*A_TOTAL)/4;                      // 79941 (exact)
    if (q >= NQ) return;
    float4 v = ((const float4*)obj)[q];
    int e0 = q*4;
    #pragma unroll
    for (int j=0;j<4;j++){
        int e = e0 + j;
        int b = (e >= A_TOTAL) ? 1 : 0;
        int a = e - b*A_TOTAL;
        int task = b*NLEV + levelOf(a);
        float f = j==0?v.x : j==1?v.y : j==2?v.z : v.w;
        atomicAdd(&g_hist[task*NB + (fkey(f) >> KSHIFT)], 1u);
    }
}

// ---------------- K2: find threshold bin per task (1024 thr, 8 bins each) ----------------
__global__ void k_scan(){
    int task = blockIdx.x;
    int lev  = task % NLEV;
    int n = levN(lev);
    int k = n < PRE_TOPN ? n : PRE_TOPN;
    __shared__ unsigned ssum[1024];
    int t = threadIdx.x;
    const uint4* hb = (const uint4*)(g_hist + (size_t)task*NB + t*8);
    uint4 h0 = hb[0], h1 = hb[1];
    unsigned own = h0.x+h0.y+h0.z+h0.w + h1.x+h1.y+h1.z+h1.w;
    ssum[t] = own;
    __syncthreads();
    // inclusive suffix scan
    for (int off=1; off<1024; off<<=1){
        unsigned v = (t+off<1024) ? ssum[t+off] : 0u;
        __syncthreads();
        ssum[t] += v;
        __syncthreads();
    }
    unsigned above = (t<1023) ? ssum[t+1] : 0u;
    if (k >= n){
        if (t==0) g_thrBin[task] = -1;    // select all
    } else if (above < (unsigned)k && above + own >= (unsigned)k){
        unsigned cnt[8] = {h0.x,h0.y,h0.z,h0.w,h1.x,h1.y,h1.z,h1.w};
        unsigned cum = above;
        #pragma unroll
        for (int j=7;j>=0;j--){
            cum += cnt[j];
            if (cum >= (unsigned)k){ g_thrBin[task] = t*8 + j; break; }
        }
    }
}

// ---------------- K3: compaction (float4) ----------------
__global__ void k_compact(const float* __restrict__ obj){
    int q = blockIdx.x*blockDim.x + threadIdx.x;
    const int NQ = (BS*A_TOTAL)/4;
    if (q >= NQ) return;
    float4 v = ((const float4*)obj)[q];
    int e0 = q*4;
    #pragma unroll
    for (int j=0;j<4;j++){
        int e = e0 + j;
        int b = (e >= A_TOTAL) ? 1 : 0;
        int a = e - b*A_TOTAL;
        int task = b*NLEV + levelOf(a);
        float f = j==0?v.x : j==1?v.y : j==2?v.z : v.w;
        unsigned key = fkey(f);
        int bin = (int)(key >> KSHIFT);
        int thr = g_thrBin[task];
        if (bin < thr) continue;
        unsigned long long packed =
            ((unsigned long long)key << 32) | (unsigned long long)(0xFFFFFFFFu - (unsigned)a);
        if (bin > thr){
            int p = atomicAdd(&g_selCnt[task], 1);
            g_sel[task*NPAD + p] = packed;
        } else {
            int p = atomicAdd(&g_tieCnt[task], 1);
            if (p < TIECAP) g_tie[task*TIECAP + p] = packed;
        }
    }
}

// ---------------- K4: resolve ties (rank-by-count), hybrid bitonic, decode+clip ----------------
__global__ void k_gather(const float* __restrict__ pred, const float* __restrict__ obj,
                         const float* __restrict__ anch, const float* __restrict__ vsz){
    __shared__ unsigned long long ss[NPAD];       // 8 KB
    __shared__ unsigned long long sties[TIECAP];  // 16 KB
    int task = blockIdx.x;
    int img = task / NLEV, lev = task % NLEV;
    int n = levN(lev);
    int k = n < PRE_TOPN ? n : PRE_TOPN;
    int tid = threadIdx.x;
    int selCnt = g_selCnt[task];
    int tc = g_tieCnt[task]; if (tc > TIECAP) tc = TIECAP;
    int need = k - selCnt;
    ss[tid] = (tid < selCnt) ? g_sel[task*NPAD + tid] : 0ull;
    if (tid < tc) sties[tid] = g_tie[task*TIECAP + tid];
    if (tid + 1024 < tc) sties[tid+1024] = g_tie[task*TIECAP + tid + 1024];
    __syncthreads();
    if (need > 0){
        for (int i = tid; i < tc; i += 1024){
            unsigned long long mine = sties[i];
            int rank = 0;
            for (int j=0;j<tc;j++) rank += (sties[j] > mine);
            if (rank < need) ss[selCnt + rank] = mine;
        }
        __syncthreads();
    }
    // hybrid bitonic (descending): smem for stride>=32, shfl below
    unsigned long long v = ss[tid];
    for (int size=2; size<=NPAD; size<<=1){
        bool dirDesc = (tid & size) == 0;
        for (int stride=size>>1; stride>=32; stride>>=1){
            __syncthreads();
            ss[tid] = v;
            __syncthreads();
            unsigned long long o = ss[tid ^ stride];
            bool takeMax = (dirDesc == ((tid & stride) == 0));
            v = takeMax ? (v > o ? v : o) : (v < o ? v : o);
        }
        int s0 = (size>>1) < 16 ? (size>>1) : 16;
        for (int stride=s0; stride>=1; stride>>=1){
            unsigned long long o = __shfl_xor_sync(0xffffffffu, v, stride);
            bool takeMax = (dirDesc == ((tid & stride) == 0));
            v = takeMax ? (v > o ? v : o) : (v < o ? v : o);
        }
    }
    int r = tid;
    float4 box = make_float4(0.f,0.f,0.f,0.f);
    float score = 0.f; unsigned key = 0u; bool valid = false;
    if (r < k){
        key = (unsigned)(v >> 32);
        unsigned a = 0xFFFFFFFFu - (unsigned)(v & 0xFFFFFFFFull);
        float4 p  = __ldg(((const float4*)pred) + ((size_t)img*A_TOTAL + a));
        float4 an = __ldg(((const float4*)anch) + a);
        float awx = an.z - an.x, awy = an.w - an.y;
        float cx = an.x + 0.5f*awx + p.x*awx;
        float cy = an.y + 0.5f*awy + p.y*awy;
        float wx = expf(p.z)*awx;
        float wy = expf(p.w)*awy;
        float x1 = cx - 0.5f*wx, y1 = cy - 0.5f*wy;
        float x2 = x1 + wx,      y2 = y1 + wy;
        float W = vsz[img*2+0], H = vsz[img*2+1];
        x1 = fminf(fmaxf(x1,0.f),W); x2 = fminf(fmaxf(x2,0.f),W);
        y1 = fminf(fmaxf(y1,0.f),H); y2 = fminf(fmaxf(y2,0.f),H);
        box = make_float4(x1,y1,x2,y2);
        valid = (x2 - x1 > 0.001f) && (y2 - y1 > 0.001f);
        score = obj[(size_t)img*A_TOTAL + a];
    }
    g_boxes [task*NPAD + r] = box;
    g_scores[task*NPAD + r] = score;
    g_keys  [task*NPAD + r] = key;
    unsigned vm = __ballot_sync(0xffffffffu, valid);
    if ((tid & 31) == 0) g_validMask[task*NW + (tid>>5)] = vm;
}

// ---------------- K5: exact chunked greedy NMS (on-the-fly IoU, no bitmatrix) ----------------
__device__ __forceinline__ bool iou_gt(float4 a, float aa, float4 b, float ab){
    float xx1 = fmaxf(a.x, b.x);
    float yy1 = fmaxf(a.y, b.y);
    float xx2 = fminf(a.z, b.z);
    float yy2 = fminf(a.w, b.w);
    float iw = fmaxf(xx2-xx1, 0.f);
    float ih = fmaxf(yy2-yy1, 0.f);
    float inter = iw*ih;
    float den = aa + 1e-9f + ab - inter;
    return inter > 0.7f*den;            // == (iou > 0.7), den > 0
}

__global__ void __launch_bounds__(1024) k_nms(){
    int task = blockIdx.x;
    int tid = threadIdx.x;
    int myw = tid >> 5, lane = tid & 31;

    __shared__ float4 sbox[NPAD];   // 16 KB
    __shared__ float  sar [NPAD];   //  4 KB
    __shared__ unsigned skeep[NW];
    float4 bi = g_boxes[task*NPAD + tid];
    sbox[tid] = bi;
    float ai = (bi.z - bi.x) * (bi.w - bi.y);
    sar[tid] = ai;
    bool alive = (g_validMask[task*NW + myw] >> lane) & 1u;
    __syncthreads();

    // intra-chunk suppression mask (box-data only, fully parallel):
    // bit j set => candidate (myw*32+j), j<lane, would suppress me if kept
    unsigned diag = 0u;
    int cb = myw*32;
    #pragma unroll 8
    for (int j=0; j<32; j++){
        bool o = (j < lane) && iou_gt(bi, ai, sbox[cb + j], sar[cb + j]);
        diag |= (o ? 1u : 0u) << j;
    }

    // sequential over 32 chunks; 1 barrier per chunk
    for (int c=0; c<NW; ++c){
        if (myw >= c && alive){
            if (c > 0){
                unsigned m = skeep[c-1];          // kept set of previous chunk
                int pb = (c-1)*32;
                bool kill = false;
                while (m){
                    int f = __ffs((int)m) - 1; m &= m - 1;
                    kill |= iou_gt(bi, ai, sbox[pb + f], sar[pb + f]);
                }
                alive = !kill;
            }
        }
        if (myw == c){
            // intra-chunk greedy resolution (warp c only)
            unsigned cand = __ballot_sync(0xffffffffu, alive);
            unsigned keptc = 0u;
            while (cand){
                int f = __ffs((int)cand) - 1;
                keptc |= (1u << f);
                unsigned supf = __ballot_sync(0xffffffffu, (diag >> f) & 1u);
                cand &= ~(supf | (1u << f));
            }
            alive = (keptc >> lane) & 1u;
            if (lane == 0) skeep[c] = keptc;
        }
        __syncthreads();
    }

    // compaction (warp 0): kept list in score-descending order
    if (tid < 32){
        unsigned keepw = skeep[lane];
        unsigned cnt = __popc(keepw);
        unsigned incl = cnt;
        #pragma unroll
        for (int d=1; d<32; d<<=1){
            unsigned v2 = __shfl_up_sync(0xffffffffu, incl, d);
            if (lane >= d) incl += v2;
        }
        unsigned excl = incl - cnt;
        unsigned total = __shfl_sync(0xffffffffu, incl, 31);
        if (lane == 0) g_kcnt[task] = (int)total;
        unsigned m = keepw; int p = (int)excl;
        while (m){
            int bb = __ffs((int)m) - 1; m &= m - 1;
            int r = lane*32 + bb;
            g_kkey[task*NPAD + p] = g_keys[task*NPAD + r];
            g_kref[task*NPAD + p] = r;
            p++;
        }
    }
}

// ---------------- K6: 5-way merge by binary-search co-ranking, scatter output ----------------
__global__ void k_output(float* __restrict__ out){
    int img = blockIdx.x;
    int tid = threadIdx.x;
    __shared__ unsigned skey[NLEV*NPAD];  // 20 KB
    __shared__ int scnt[NLEV];
    if (tid < NLEV) scnt[tid] = g_kcnt[img*NLEV + tid];
    for (int lt=0; lt<NLEV; lt++)
        skey[lt*NPAD + tid] = g_kkey[(img*NLEV + lt)*NPAD + tid];
    for (int i=tid; i<POST_TOPN*4; i+=1024) out[img*POST_TOPN*4 + i] = 0.f;
    for (int i=tid; i<POST_TOPN;   i+=1024) out[BS*POST_TOPN*4 + img*POST_TOPN + i] = 0.f;
    __syncthreads();
    for (int e=tid; e<NLEV*NPAD; e+=1024){
        int lt = e >> 10, p = e & (NPAD-1);
        if (p < scnt[lt]){
            unsigned key = skey[lt*NPAD + p];
            int rank = p;
            #pragma unroll
            for (int o=0; o<NLEV; o++){
                if (o == lt) continue;
                int c = scnt[o];
                const unsigned* arr = skey + o*NPAD;
                int lo=0, hi=c;
                while (lo < hi){
                    int mid = (lo+hi) >> 1;
                    bool before = (o < lt) ? (arr[mid] >= key) : (arr[mid] > key);
                    if (before) lo = mid+1; else hi = mid;
                }
                rank += lo;
            }
            if (rank < POST_TOPN){
                int task = img*NLEV + lt;
                int r = g_kref[task*NPAD + p];
                float4 bb = g_boxes[task*NPAD + r];
                float sc  = g_scores[task*NPAD + r];
                float* ob = out + (img*POST_TOPN + rank)*4;
                ob[0]=bb.x; ob[1]=bb.y; ob[2]=bb.z; ob[3]=bb.w;
                out[BS*POST_TOPN*4 + img*POST_TOPN + rank] = sc;
            }
        }
    }
}

// ---------------- launch ----------------
extern "C" void kernel_launch(void* const* d_in, const int* in_sizes, int n_in,
                              void* d_out, int out_size){
    const float* pred = (const float*)d_in[0];   // (2, A, 4)
    const float* obj  = (const float*)d_in[1];   // (2, A, 1)
    const float* anch = (const float*)d_in[2];   // (A, 4)
    const float* vsz  = (const float*)d_in[3];   // (2, 2)
    float* out = (float*)d_out;                  // [boxes(2,1000,4) | scores(2,1000)]

    const int NQ = (BS*A_TOTAL)/4;               // 79941 float4s
    k_zero   <<<(NTASK*NB/4 + 255)/256, 256>>>();
    k_hist   <<<(NQ + 255)/256, 256>>>(obj);
    k_scan   <<<NTASK, 1024>>>();
    k_compact<<<(NQ + 255)/256, 256>>>(obj);
    k_gather <<<NTASK, 1024>>>(pred, obj, anch, vsz);
    k_nms    <<<NTASK, 1024>>>();
    k_output <<<BS, 1024>>>(out);
}

// round 7
// speedup vs baseline: 2.6168x; 2.3410x over previous
#include <cuda_runtime.h>
#include <stdint.h>

// ---------------- problem constants ----------------
#define A_TOTAL   159882
#define BS        2
#define NLEV      5
#define NTASK     (BS*NLEV)
#define NPAD      1024
#define NW        32           // 1024 bits / 32
#define NB        65536        // histogram bins (top 16 bits of monotone key)
#define KSHIFT    16
#define TIECAP    4096
#define PRE_TOPN  1000
#define POST_TOPN 1000

// level boundaries: 120000,30000,7500,1875,507
__device__ __forceinline__ int levelOf(int a){
    if (a < 120000) return 0;
    if (a < 150000) return 1;
    if (a < 157500) return 2;
    if (a < 159375) return 3;
    return 4;
}
__device__ __forceinline__ int levN(int l){
    const int n0 = 120000, n1 = 30000, n2 = 7500, n3 = 1875, n4 = 507;
    return l==0?n0 : l==1?n1 : l==2?n2 : l==3?n3 : n4;
}

// monotone key: larger float -> larger unsigned
__device__ __forceinline__ unsigned fkey(float f){
    unsigned u = __float_as_uint(f);
    return (u & 0x80000000u) ? ~u : (u | 0x80000000u);
}

// ---------------- scratch (device globals; no allocation) ----------------
__device__ __align__(16) unsigned            g_hist[NTASK*NB];      // 2.62 MB
__device__ int                               g_tieCnt[NTASK];
__device__ int                               g_selCnt[NTASK];
__device__ int                               g_thrBin[NTASK];
__device__ __align__(16) unsigned long long  g_tie[NTASK*TIECAP];
__device__ __align__(16) unsigned long long  g_sel[NTASK*NPAD];
__device__ __align__(16) float4              g_boxes[NTASK*NPAD];
__device__ float                             g_scores[NTASK*NPAD];
__device__ unsigned                          g_keys[NTASK*NPAD];
__device__ unsigned                          g_validMask[NTASK*NW];
__device__ __align__(16) unsigned            g_sup[NTASK*NPAD*NW];  // 1.31 MB
__device__ int                               g_kcnt[NTASK];
__device__ unsigned                          g_kkey[NTASK*NPAD];
__device__ int                               g_kref[NTASK*NPAD];

// ---------------- K0: zero histogram + counters (vectorized) ----------------
__global__ void k_zero(){
    int i = blockIdx.x*blockDim.x + threadIdx.x;
    uint4 z = make_uint4(0,0,0,0);
    if (i < NTASK*NB/4) ((uint4*)g_hist)[i] = z;
    if (i < NTASK){ g_tieCnt[i] = 0; g_selCnt[i] = 0; }
}

// ---------------- K1: per-task 65536-bin histogram (float4) ----------------
__global__ void k_hist(const float* __restrict__ obj){
    int q = blockIdx.x*blockDim.x + threadIdx.x;       // float4 index
    const int NQ = (BS*A_TOTAL)/4;                      // 79941 (exact)
    if (q >= NQ) return;
    float4 v = ((const float4*)obj)[q];
    int e0 = q*4;
    #pragma unroll
    for (int j=0;j<4;j++){
        int e = e0 + j;
        int b = (e >= A_TOTAL) ? 1 : 0;
        int a = e - b*A_TOTAL;
        int task = b*NLEV + levelOf(a);
        float f = j==0?v.x : j==1?v.y : j==2?v.z : v.w;
        atomicAdd(&g_hist[task*NB + (fkey(f) >> KSHIFT)], 1u);
    }
}

// ---------------- K2: find threshold bin per task (1024 thr, 64 bins each) ----------------
__global__ void k_scan(){
    int task = blockIdx.x;
    int lev  = task % NLEV;
    int n = levN(lev);
    int k = n < PRE_TOPN ? n : PRE_TOPN;
    __shared__ unsigned ssum[1024];
    int t = threadIdx.x;
    unsigned own = 0;
    const uint4* hb = (const uint4*)(g_hist + (size_t)task*NB + t*64);
    #pragma unroll
    for (int i=0;i<16;i++){ uint4 h = hb[i]; own += h.x+h.y+h.z+h.w; }
    ssum[t] = own;
    __syncthreads();
    // inclusive suffix scan over 1024 partial sums
    for (int off=1; off<1024; off<<=1){
        unsigned v = (t+off<1024) ? ssum[t+off] : 0u;
        __syncthreads();
        ssum[t] += v;
        __syncthreads();
    }
    unsigned above = (t<1023) ? ssum[t+1] : 0u;
    if (k >= n){
        if (t==0) g_thrBin[task] = -1;    // select all
    } else if (above < (unsigned)k && above + own >= (unsigned)k){
        unsigned cum = above;
        for (int b2 = t*64+63; b2 >= t*64; --b2){
            cum += g_hist[(size_t)task*NB + b2];
            if (cum >= (unsigned)k){ g_thrBin[task] = b2; break; }
        }
    }
}

// ---------------- K3: compaction (float4) ----------------
__global__ void k_compact(const float* __restrict__ obj){
    int q = blockIdx.x*blockDim.x + threadIdx.x;
    const int NQ = (BS*A_TOTAL)/4;
    if (q >= NQ) return;
    float4 v = ((const float4*)obj)[q];
    int e0 = q*4;
    #pragma unroll
    for (int j=0;j<4;j++){
        int e = e0 + j;
        int b = (e >= A_TOTAL) ? 1 : 0;
        int a = e - b*A_TOTAL;
        int task = b*NLEV + levelOf(a);
        float f = j==0?v.x : j==1?v.y : j==2?v.z : v.w;
        unsigned key = fkey(f);
        int bin = (int)(key >> KSHIFT);
        int thr = g_thrBin[task];
        if (bin < thr) continue;
        unsigned long long packed =
            ((unsigned long long)key << 32) | (unsigned long long)(0xFFFFFFFFu - (unsigned)a);
        if (bin > thr){
            int p = atomicAdd(&g_selCnt[task], 1);
            g_sel[task*NPAD + p] = packed;
        } else {
            int p = atomicAdd(&g_tieCnt[task], 1);
            if (p < TIECAP) g_tie[task*TIECAP + p] = packed;
        }
    }
}

// ---------------- bitonic sort (descending) for 1024 elems, 1024 threads ----------------
__device__ void bitonic_desc1024(unsigned long long* s, int tid){
    for (int size=2; size<=NPAD; size<<=1){
        for (int stride=size>>1; stride>0; stride>>=1){
            __syncthreads();
            int j = tid ^ stride;
            if (j > tid){
                bool dirDesc = ((tid & size) == 0);
                unsigned long long x = s[tid], y = s[j];
                bool sw = dirDesc ? (x < y) : (x > y);
                if (sw){ s[tid] = y; s[j] = x; }
            }
        }
    }
    __syncthreads();
}

// ---------------- K4: resolve ties (rank-by-count), sort, gather+decode+clip ----------------
__global__ void k_gather(const float* __restrict__ pred, const float* __restrict__ obj,
                         const float* __restrict__ anch, const float* __restrict__ vsz){
    __shared__ unsigned long long ss[NPAD];       //  8 KB
    __shared__ unsigned long long sties[TIECAP];  // 32 KB
    int task = blockIdx.x;
    int img = task / NLEV, lev = task % NLEV;
    int n = levN(lev);
    int k = n < PRE_TOPN ? n : PRE_TOPN;
    int tid = threadIdx.x;
    int selCnt = g_selCnt[task];
    int tc = g_tieCnt[task]; if (tc > TIECAP) tc = TIECAP;
    int need = k - selCnt;
    ss[tid] = (tid < selCnt) ? g_sel[task*NPAD + tid] : 0ull;
    for (int i = tid; i < tc; i += 1024) sties[i] = g_tie[task*TIECAP + i];
    __syncthreads();
    if (need > 0){
        // rank-by-count: keys are unique (anchor idx packed in low bits) -> unique ranks
        for (int i = tid; i < tc; i += 1024){
            unsigned long long mine = sties[i];
            int rank = 0;
            for (int j=0;j<tc;j++) rank += (sties[j] > mine);
            if (rank < need) ss[selCnt + rank] = mine;
        }
        __syncthreads();
    }
    // sort the k selected (padded to 1024 with 0-keys, which sort last)
    bitonic_desc1024(ss, tid);

    int r = tid;
    float4 box = make_float4(0.f,0.f,0.f,0.f);
    float score = 0.f; unsigned key = 0u; bool valid = false;
    if (r < k){
        unsigned long long v = ss[r];
        key = (unsigned)(v >> 32);
        unsigned a = 0xFFFFFFFFu - (unsigned)(v & 0xFFFFFFFFull);
        float4 p  = __ldg(((const float4*)pred) + ((size_t)img*A_TOTAL + a));
        float4 an = __ldg(((const float4*)anch) + a);
        float awx = an.z - an.x, awy = an.w - an.y;
        float cx = an.x + 0.5f*awx + p.x*awx;
        float cy = an.y + 0.5f*awy + p.y*awy;
        float wx = expf(p.z)*awx;
        float wy = expf(p.w)*awy;
        float x1 = cx - 0.5f*wx, y1 = cy - 0.5f*wy;
        float x2 = x1 + wx,      y2 = y1 + wy;
        float W = vsz[img*2+0], H = vsz[img*2+1];
        x1 = fminf(fmaxf(x1,0.f),W); x2 = fminf(fmaxf(x2,0.f),W);
        y1 = fminf(fmaxf(y1,0.f),H); y2 = fminf(fmaxf(y2,0.f),H);
        box = make_float4(x1,y1,x2,y2);
        valid = (x2 - x1 > 0.001f) && (y2 - y1 > 0.001f);
        score = obj[(size_t)img*A_TOTAL + a];
    }
    g_boxes [task*NPAD + r] = box;
    g_scores[task*NPAD + r] = score;
    g_keys  [task*NPAD + r] = key;
    unsigned vm = __ballot_sync(0xffffffffu, valid);
    if ((tid & 31) == 0) g_validMask[task*NW + (tid>>5)] = vm;
}

// ---------------- K5: suppression bit-matrix (IoU > 0.7, division-free) ----------------
__global__ void k_supmat(){
    int task = blockIdx.y;
    __shared__ float4 sbox[NPAD];   // 16 KB
    __shared__ float  sar [NPAD];   //  4 KB
    int tid = threadIdx.x;
    for (int j=tid; j<NPAD; j+=256){
        float4 bb = g_boxes[task*NPAD + j];
        sbox[j] = bb;
        sar[j]  = (bb.z - bb.x) * (bb.w - bb.y);
    }
    __syncthreads();
    int wid = tid >> 5, lane = tid & 31;
    int i = blockIdx.x*8 + wid;            // row
    float4 bi = sbox[i];
    float tden = sar[i] + 1e-9f;
    unsigned* dst = &g_sup[((size_t)task*NPAD + i)*NW];
    #pragma unroll 4
    for (int jw=0; jw<NW; jw++){
        int j = jw*32 + lane;
        float4 bj = sbox[j];
        float xx1 = fmaxf(bi.x, bj.x);
        float yy1 = fmaxf(bi.y, bj.y);
        float xx2 = fminf(bi.z, bj.z);
        float yy2 = fminf(bi.w, bj.w);
        float iw = fmaxf(xx2-xx1, 0.f);
        float ih = fmaxf(yy2-yy1, 0.f);
        float inter = iw*ih;
        float den = tden + sar[j] - inter;
        bool sup = inter > 0.7f*den;        // == (iou > 0.7)
        unsigned m = __ballot_sync(0xffffffffu, sup);
        if (lane == 0) dst[jw] = m;
    }
}

// ---------------- K6: exact fixed-point NMS (parallel), sequential fallback ----------------
__global__ void k_nms(){
    int task = blockIdx.x;
    int tid = threadIdx.x;            // candidate index i
    int myw = tid >> 5, lane = tid & 31;
    unsigned row[NW];
    const uint4* rp = (const uint4*)(g_sup + ((size_t)task*NPAD + tid)*NW);
    #pragma unroll
    for (int q=0;q<8;q++){
        uint4 v = rp[q];
        row[q*4+0]=v.x; row[q*4+1]=v.y; row[q*4+2]=v.z; row[q*4+3]=v.w;
    }
    #pragma unroll
    for (int w=0;w<NW;w++) if (w > myw) row[w] = 0u;
    row[myw] &= (lane ? ((1u<<lane)-1u) : 0u);
    bool valid = (g_validMask[task*NW + myw] >> lane) & 1u;

    __shared__ unsigned skeep[NW];
    __shared__ int schanged, sconv;
    if (tid < NW) skeep[tid] = g_validMask[task*NW + tid];
    if (tid == 0) sconv = 0;
    __syncthreads();

    for (int it=0; it<24; ++it){
        unsigned any = 0u;
        #pragma unroll
        for (int w=0;w<NW;w++) any |= row[w] & skeep[w];
        bool nk = valid && (any == 0u);
        unsigned bw = __ballot_sync(0xffffffffu, nk);
        if (tid == 0) schanged = 0;
        __syncthreads();
        if (lane == 0){
            if (bw != skeep[myw]) schanged = 1;
            skeep[myw] = bw;
        }
        __syncthreads();
        if (!schanged){ if (tid==0) sconv = 1; break; }
    }
    __syncthreads();

    if (!sconv){
        // deterministic sequential fallback (warp 0), exact greedy sweep
        if (tid < 32){
            unsigned validw = g_validMask[task*NW + lane];
            const unsigned* rowbase = g_sup + (size_t)task*NPAD*NW;
            unsigned removed = 0u, keepw = 0u;
            unsigned ring[8];
            #pragma unroll
            for (int d=0; d<8; d++) ring[d] = rowbase[d*NW + lane];
            for (int ib=0; ib<NPAD; ib+=8){
                #pragma unroll
                for (int u=0; u<8; u++){
                    int i = ib + u;
                    unsigned live = (~removed) & validw;
                    unsigned cand = __shfl_sync(0xffffffffu, live, i>>5);
                    unsigned take = (cand >> (i & 31)) & 1u;
                    unsigned mask = (unsigned)(-(int)take);
                    removed |= ring[u] & mask;
                    if (lane == (i>>5)) keepw |= (take << (i & 31));
                    int nx = i + 8;
                    ring[u] = (nx < NPAD) ? rowbase[nx*NW + lane] : 0u;
                }
            }
            skeep[lane] = keepw;
        }
        __syncthreads();
    }

    // compaction (warp 0): kept list in score-descending order
    if (tid < 32){
        unsigned keepw = skeep[lane];
        unsigned cnt = __popc(keepw);
        unsigned incl = cnt;
        #pragma unroll
        for (int d=1; d<32; d<<=1){
            unsigned v = __shfl_up_sync(0xffffffffu, incl, d);
            if (lane >= d) incl += v;
        }
        unsigned excl = incl - cnt;
        unsigned total = __shfl_sync(0xffffffffu, incl, 31);
        if (lane == 0) g_kcnt[task] = (int)total;
        unsigned m = keepw; int p = (int)excl;
        while (m){
            int b = __ffs((int)m) - 1; m &= m - 1;
            int r = lane*32 + b;
            g_kkey[task*NPAD + p] = g_keys[task*NPAD + r];
            g_kref[task*NPAD + p] = r;
            p++;
        }
    }
}

// ---------------- K7: 5-way merge by binary-search co-ranking, scatter output ----------------
__global__ void k_output(float* __restrict__ out){
    int img = blockIdx.x;
    int tid = threadIdx.x;
    __shared__ unsigned skey[NLEV*NPAD];  // 20 KB
    __shared__ int scnt[NLEV];
    if (tid < NLEV) scnt[tid] = g_kcnt[img*NLEV + tid];
    for (int lt=0; lt<NLEV; lt++)
        skey[lt*NPAD + tid] = g_kkey[(img*NLEV + lt)*NPAD + tid];
    for (int i=tid; i<POST_TOPN*4; i+=1024) out[img*POST_TOPN*4 + i] = 0.f;
    for (int i=tid; i<POST_TOPN;   i+=1024) out[BS*POST_TOPN*4 + img*POST_TOPN + i] = 0.f;
    __syncthreads();
    for (int e=tid; e<NLEV*NPAD; e+=1024){
        int lt = e >> 10, p = e & (NPAD-1);
        if (p < scnt[lt]){
            unsigned key = skey[lt*NPAD + p];
            int rank = p;
            #pragma unroll
            for (int o=0; o<NLEV; o++){
                if (o == lt) continue;
                int c = scnt[o];
                const unsigned* arr = skey + o*NPAD;
                int lo=0, hi=c;
                while (lo < hi){
                    int mid = (lo+hi) >> 1;
                    bool before = (o < lt) ? (arr[mid] >= key) : (arr[mid] > key);
                    if (before) lo = mid+1; else hi = mid;
                }
                rank += lo;
            }
            if (rank < POST_TOPN){
                int task = img*NLEV + lt;
                int r = g_kref[task*NPAD + p];
                float4 bb = g_boxes[task*NPAD + r];
                float sc  = g_scores[task*NPAD + r];
                float* ob = out + (img*POST_TOPN + rank)*4;
                ob[0]=bb.x; ob[1]=bb.y; ob[2]=bb.z; ob[3]=bb.w;
                out[BS*POST_TOPN*4 + img*POST_TOPN + rank] = sc;
            }
        }
    }
}

// ---------------- launch ----------------
extern "C" void kernel_launch(void* const* d_in, const int* in_sizes, int n_in,
                              void* d_out, int out_size){
    const float* pred = (const float*)d_in[0];   // (2, A, 4)
    const float* obj  = (const float*)d_in[1];   // (2, A, 1)
    const float* anch = (const float*)d_in[2];   // (A, 4)
    const float* vsz  = (const float*)d_in[3];   // (2, 2)
    float* out = (float*)d_out;                  // [boxes(2,1000,4) | scores(2,1000)]

    const int NQ = (BS*A_TOTAL)/4;               // 79941 float4s
    k_zero   <<<(NTASK*NB/4 + 255)/256, 256>>>();
    k_hist   <<<(NQ + 255)/256, 256>>>(obj);
    k_scan   <<<NTASK, 1024>>>();
    k_compact<<<(NQ + 255)/256, 256>>>(obj);
    k_gather <<<NTASK, 1024>>>(pred, obj, anch, vsz);
    k_supmat <<<dim3(NPAD/8, NTASK), 256>>>();
    k_nms    <<<NTASK, 1024>>>();
    k_output <<<BS, 1024>>>(out);
}